// round 13
// baseline (speedup 1.0000x reference)
#include <cuda_runtime.h>
#include <math.h>

#define FULLMASK 0xFFFFFFFFu

// ---------------- scratch (no allocations allowed) ----------------
__device__ double g_acc[8];            // 0..2 ifd0..2, 3..4 scr0..1
__device__ double g_main_part[32];
__device__ float  g_np0[32 * 32 * 64];   // norm partials [b][strip][c]
__device__ float  g_np1[32 * 16 * 128];
__device__ float  g_np2[32 * 8 * 256];
__device__ float  g_ps0[32 * 16384];     // per-pixel all-channel sums
__device__ float  g_ps1[32 * 4096];
__device__ float  g_ps2[32 * 1024];
__device__ int    g_done;                // passB completion counter

struct Sel { int s0[64]; int s1[128]; };

__device__ __forceinline__ void warp_red(float& s) {
  for (int o = 16; o; o >>= 1) s += __shfl_down_sync(FULLMASK, s, o);
}

__device__ __forceinline__ void block_add_double(float val, int slot, double* shd,
                                                 bool count_done) {
  double d = (double)val;
  for (int o = 16; o; o >>= 1) d += __shfl_down_sync(FULLMASK, d, o);
  int t = threadIdx.x, w = t >> 5;
  if ((t & 31) == 0) shd[w] = d;
  __syncthreads();
  if (t == 0) {
    double s = 0.0;
    for (int i = 0; i < 8; i++) s += shd[i];
    atomicAdd(&g_acc[slot], s);
    if (count_done) {
      __threadfence();
      atomicAdd(&g_done, 1);
    }
  }
}

// =========================== PASS A (R11 bodies: reg-lean) ===========================

// f0: block=(b, strip s of 512px = 4 rows of 128). 8 warps x 8 channels.
__device__ void passa_f0(float* buf, double* shd, const float* __restrict__ f0,
                         const float* __restrict__ f2, const Sel& sel, int b, int s) {
  int t = threadIdx.x, w = t >> 5, lane = t & 31;
  const float* base = f0 + (size_t)b * 64 * 16384 + s * 512;
  const float* tb = f2 + (size_t)b * 256 * 1024 + s * 32;  // texel row == s
  float4 ps[4];
#pragma unroll
  for (int q = 0; q < 4; q++) ps[q] = make_float4(0.f, 0.f, 0.f, 0.f);
  float scr = 0.f;
#pragma unroll
  for (int r = 0; r < 8; r++) {
    int c = w * 8 + r;
    const float4* pc = (const float4*)(base + (size_t)c * 16384);
    float tv = tb[(size_t)sel.s0[c] * 1024 + lane];
    float nn = 0.f;
#pragma unroll
    for (int q = 0; q < 4; q++) {
      float4 v = pc[lane + 32 * q];
      ps[q].x += v.x; ps[q].y += v.y; ps[q].z += v.z; ps[q].w += v.w;
      nn += v.x * v.x + v.y * v.y + v.z * v.z + v.w * v.w;
      float d0 = v.x - tv, d1 = v.y - tv, d2 = v.z - tv, d3 = v.w - tv;
      scr += d0 * d0 + d1 * d1 + d2 * d2 + d3 * d3;
    }
    warp_red(nn);                              // inline: frees n[] registers
    if (lane == 0) g_np0[((b * 32 + s) * 64) + c] = nn;
  }
  float4* b4 = (float4*)(buf + w * 512);
#pragma unroll
  for (int q = 0; q < 4; q++) b4[lane + 32 * q] = ps[q];
  __syncthreads();
  float* gp = g_ps0 + (size_t)b * 16384 + s * 512;
  for (int p = t; p < 512; p += 256) {
    float ss = 0.f;
#pragma unroll
    for (int w2 = 0; w2 < 8; w2++) ss += buf[w2 * 512 + p];
    gp[p] = ss;
  }
  block_add_double(scr, 3, shd, false);
}

// f1: block=(b, strip s of 256px = 4 rows of 64). 8 warps x 16 channels.
__device__ void passa_f1(float* buf, double* shd, const float* __restrict__ f1,
                         const float* __restrict__ f2, const Sel& sel, int b, int s) {
  int t = threadIdx.x, w = t >> 5, lane = t & 31;
  const float* base = f1 + (size_t)b * 128 * 4096 + s * 256;
  const float* tb = f2 + (size_t)b * 256 * 1024;
  int tcol = (2 * lane) & 31;
  float4 ps0 = make_float4(0.f, 0.f, 0.f, 0.f), ps1 = ps0;
  float scr = 0.f;
#pragma unroll
  for (int r = 0; r < 16; r++) {
    int c = w * 16 + r;
    const float4* pc = (const float4*)(base + (size_t)c * 4096);
    const float* tc = tb + (size_t)sel.s1[c] * 1024;
    float2 t0 = *(const float2*)(tc + (2 * s) * 32 + tcol);
    float2 t1 = *(const float2*)(tc + (2 * s + 1) * 32 + tcol);
    float4 v0 = pc[lane];
    float4 v1 = pc[lane + 32];
    ps0.x += v0.x; ps0.y += v0.y; ps0.z += v0.z; ps0.w += v0.w;
    ps1.x += v1.x; ps1.y += v1.y; ps1.z += v1.z; ps1.w += v1.w;
    float nn = v0.x * v0.x + v0.y * v0.y + v0.z * v0.z + v0.w * v0.w
             + v1.x * v1.x + v1.y * v1.y + v1.z * v1.z + v1.w * v1.w;
    float a0 = v0.x - t0.x, a1 = v0.y - t0.x, a2 = v0.z - t0.y, a3 = v0.w - t0.y;
    float b0 = v1.x - t1.x, b1 = v1.y - t1.x, b2 = v1.z - t1.y, b3 = v1.w - t1.y;
    scr += a0 * a0 + a1 * a1 + a2 * a2 + a3 * a3
         + b0 * b0 + b1 * b1 + b2 * b2 + b3 * b3;
    warp_red(nn);
    if (lane == 0) g_np1[((b * 16 + s) * 128) + c] = nn;
  }
  float4* b4 = (float4*)(buf + w * 256);
  b4[lane] = ps0;
  b4[lane + 32] = ps1;
  __syncthreads();
  float* gp = g_ps1 + (size_t)b * 4096 + s * 256;
  if (t < 256) {
    float ss = 0.f;
#pragma unroll
    for (int w2 = 0; w2 < 8; w2++) ss += buf[w2 * 256 + t];
    gp[t] = ss;
  }
  block_add_double(scr, 4, shd, false);
}

// f2: block=(b, strip s of 128px). 8 warps x 32 channels. no teacher.
__device__ void passa_f2(float* buf, const float* __restrict__ f2, int b, int s) {
  int t = threadIdx.x, w = t >> 5, lane = t & 31;
  const float* base = f2 + (size_t)b * 256 * 1024 + s * 128;
  float4 ps = make_float4(0.f, 0.f, 0.f, 0.f);
#pragma unroll
  for (int g = 0; g < 4; g++) {
#pragma unroll
    for (int r = 0; r < 8; r++) {
      int c = w * 32 + g * 8 + r;
      float4 v = ((const float4*)(base + (size_t)c * 1024))[lane];
      ps.x += v.x; ps.y += v.y; ps.z += v.z; ps.w += v.w;
      float nn = v.x * v.x + v.y * v.y + v.z * v.z + v.w * v.w;
      warp_red(nn);
      if (lane == 0) g_np2[((b * 8 + s) * 256) + c] = nn;
    }
  }
  float4* b4 = (float4*)(buf + w * 128);
  b4[lane] = ps;
  __syncthreads();
  float* gp = g_ps2 + (size_t)b * 1024 + s * 128;
  if (t < 128) {
    float ss = 0.f;
#pragma unroll
    for (int w2 = 0; w2 < 8; w2++) ss += buf[w2 * 128 + t];
    gp[t] = ss;
  }
}

// l_main
__device__ void main_body(const float* __restrict__ pred, const int* __restrict__ tgt, int b) {
  __shared__ float sh[8];
  __shared__ float shm;
  int t = threadIdx.x;
  const float* row = pred + b * 1000;
  float m = -1e30f;
  for (int i = t; i < 1000; i += 256) m = fmaxf(m, row[i]);
  for (int o = 16; o; o >>= 1) m = fmaxf(m, __shfl_down_sync(FULLMASK, m, o));
  if ((t & 31) == 0) sh[t >> 5] = m;
  __syncthreads();
  if (t == 0) {
    float mm = sh[0];
    for (int i = 1; i < 8; i++) mm = fmaxf(mm, sh[i]);
    shm = mm;
  }
  __syncthreads();
  m = shm;
  float s = 0.f;
  for (int i = t; i < 1000; i += 256) s += expf(row[i] - m);
  for (int o = 16; o; o >>= 1) s += __shfl_down_sync(FULLMASK, s, o);
  if ((t & 31) == 0) sh[t >> 5] = s;
  __syncthreads();
  if (t == 0) {
    float ss = 0.f;
    for (int i = 0; i < 8; i++) ss += sh[i];
    int tg = tgt[b];
    double lp = (double)(row[tg] - m) - log((double)ss);
    g_main_part[b] = -lp;
  }
}

__global__ void __launch_bounds__(256, 5) k_passA(
    const float* __restrict__ pred, const float* __restrict__ f0,
    const float* __restrict__ f1, const float* __restrict__ f2,
    const int* __restrict__ tgt, Sel sel) {
  __shared__ __align__(16) float buf[8 * 512];
  __shared__ double shd[8];
  int bid = blockIdx.x;
  if (bid < 1024) { passa_f0(buf, shd, f0, f2, sel, bid >> 5, bid & 31); return; }
  bid -= 1024;
  if (bid < 512)  { passa_f1(buf, shd, f1, f2, sel, bid >> 4, bid & 15); return; }
  bid -= 512;
  if (bid < 256)  { passa_f2(buf, f2, bid >> 3, bid & 7); return; }
  bid -= 256;
  main_body(pred, tgt, bid);
}

// =========================== PASS B (R10 bodies, unroll 8) ===========================

template <int C>
__device__ __forceinline__ void rank_strong(const float* ns, int* sidx) {
  int t = threadIdx.x;
  if (t < C) {
    float v = ns[t];
    int rank = 0;
#pragma unroll 4
    for (int j = 0; j < C; j++) {
      float nj = ns[j];
      rank += (nj > v) || (nj == v && j < t);   // argsort(-norm), stable
    }
    if (rank < C / 2) sidx[rank] = t;
  }
  __syncthreads();
}

__device__ __forceinline__ float sigmoidf_(float x) { return 1.f / (1.f + expf(-x)); }

// f0: 16 blocks/batch, vec4 (1024 px/block), 32 strong planes
__device__ void passb_f0(const float* __restrict__ f0, int b, int pb,
                         float* ns, int* sidx, double* shd) {
  int t = threadIdx.x;
  if (t < 64) {
    float s = 0.f;
    const float* pp = g_np0 + b * 32 * 64 + t;
#pragma unroll 8
    for (int k = 0; k < 32; k++) s += pp[k * 64];
    ns[t] = s;
  }
  __syncthreads();
  rank_strong<64>(ns, sidx);
  int p0 = pb * 1024 + t * 4;
  const float* xb = f0 + (size_t)b * 64 * 16384 + p0;
  float s0 = 0.f, s1 = 0.f, s2 = 0.f, s3 = 0.f;
#pragma unroll 8
  for (int k = 0; k < 32; k++) {
    float4 v = *(const float4*)(xb + (size_t)sidx[k] * 16384);
    s0 += v.x; s1 += v.y; s2 += v.z; s3 += v.w;
  }
  float4 pa = *(const float4*)(g_ps0 + (size_t)b * 16384 + p0);
  const float inv = 1.f / 32.f;
  float d0 = sigmoidf_((pa.x - s0) * inv) - sigmoidf_(s0 * inv);
  float d1 = sigmoidf_((pa.y - s1) * inv) - sigmoidf_(s1 * inv);
  float d2 = sigmoidf_((pa.z - s2) * inv) - sigmoidf_(s2 * inv);
  float d3 = sigmoidf_((pa.w - s3) * inv) - sigmoidf_(s3 * inv);
  block_add_double(d0 * d0 + d1 * d1 + d2 * d2 + d3 * d3, 0, shd, true);
}

// f1: 8 blocks/batch, vec2 (512 px/block), 64 strong planes
__device__ void passb_f1(const float* __restrict__ f1, int b, int pb,
                         float* ns, int* sidx, double* shd) {
  int t = threadIdx.x;
  if (t < 128) {
    float s = 0.f;
    const float* pp = g_np1 + b * 16 * 128 + t;
#pragma unroll 8
    for (int k = 0; k < 16; k++) s += pp[k * 128];
    ns[t] = s;
  }
  __syncthreads();
  rank_strong<128>(ns, sidx);
  int p0 = pb * 512 + t * 2;
  const float* xb = f1 + (size_t)b * 128 * 4096 + p0;
  float s0 = 0.f, s1 = 0.f;
#pragma unroll 8
  for (int k = 0; k < 64; k++) {
    float2 v = *(const float2*)(xb + (size_t)sidx[k] * 4096);
    s0 += v.x; s1 += v.y;
  }
  float2 pa = *(const float2*)(g_ps1 + (size_t)b * 4096 + p0);
  const float inv = 1.f / 64.f;
  float d0 = sigmoidf_((pa.x - s0) * inv) - sigmoidf_(s0 * inv);
  float d1 = sigmoidf_((pa.y - s1) * inv) - sigmoidf_(s1 * inv);
  block_add_double(d0 * d0 + d1 * d1, 1, shd, true);
}

// f2: 4 blocks/batch, vec1 (256 px/block), 128 strong planes
__device__ void passb_f2(const float* __restrict__ f2, int b, int pb,
                         float* ns, int* sidx, double* shd) {
  int t = threadIdx.x;
  {
    float s = 0.f;
    const float* pp = g_np2 + b * 8 * 256 + t;
#pragma unroll 8
    for (int k = 0; k < 8; k++) s += pp[k * 256];
    ns[t] = s;
  }
  __syncthreads();
  rank_strong<256>(ns, sidx);
  int p0 = pb * 256 + t;
  const float* xb = f2 + (size_t)b * 256 * 1024 + p0;
  float s0 = 0.f;
#pragma unroll 8
  for (int k = 0; k < 128; k++) {
    s0 += xb[(size_t)sidx[k] * 1024];
  }
  float pa = g_ps2[(size_t)b * 1024 + p0];
  const float inv = 1.f / 128.f;
  float d0 = sigmoidf_((pa - s0) * inv) - sigmoidf_(s0 * inv);
  block_add_double(d0 * d0, 2, shd, true);
}

// final: spins until all 896 passB work-blocks published, reduces, resets.
__device__ void final_body(float* __restrict__ out) {
  if (threadIdx.x == 0) {
    volatile int* d = &g_done;
    while (*d < 896) __nanosleep(128);
    __threadfence();
    double lm = 0.0;
    for (int i = 0; i < 32; i++) lm += g_main_part[i];
    double l_main = lm / 32.0;
    double ifd0 = g_acc[0] / (32.0 * 128.0 * 128.0);
    double ifd1 = g_acc[1] / (32.0 * 64.0 * 64.0);
    double ifd2 = g_acc[2] / (32.0 * 32.0 * 32.0);
    double l_ifd = (ifd0 + ifd1 + ifd2) / 3.0;
    double scr0 = g_acc[3] / (32.0 * 64.0 * 128.0 * 128.0);
    double scr1 = g_acc[4] / (32.0 * 128.0 * 64.0 * 64.0);
    double l_scr = (scr0 + scr1) / 2.0;
    double total = l_main + 0.015 * l_scr + 0.015 * l_ifd;
    out[0] = (float)total;
    out[1] = (float)l_main;
    out[2] = (float)l_scr;
    out[3] = (float)l_ifd;
    for (int i = 0; i < 8; i++) g_acc[i] = 0.0;   // reset for next replay
    g_done = 0;
  }
}

__global__ void __launch_bounds__(256) k_passB(
    const float* __restrict__ f0, const float* __restrict__ f1,
    const float* __restrict__ f2, float* __restrict__ out) {
  __shared__ float ns[256];
  __shared__ int sidx[128];
  __shared__ double shd[8];
  int bid = blockIdx.x;
  // f2 first (still warm in L2 from passA), then f1, then f0; final last.
  if (bid < 128) { passb_f2(f2, bid >> 2, bid & 3, ns, sidx, shd); return; }
  bid -= 128;
  if (bid < 256) { passb_f1(f1, bid >> 3, bid & 7, ns, sidx, shd); return; }
  bid -= 256;
  if (bid < 512) { passb_f0(f0, bid >> 4, bid & 15, ns, sidx, shd); return; }
  final_body(out);
}

// =========================== HOST: constant channel permutations ===========================
static void tf_h(unsigned k0, unsigned k1, unsigned x0, unsigned x1,
                 unsigned* o0, unsigned* o1) {
  unsigned ks2 = 0x1BD11BDAu ^ k0 ^ k1;
#define TFRH(r) { x0 += x1; x1 = (x1 << (r)) | (x1 >> (32 - (r))); x1 ^= x0; }
  x0 += k0; x1 += k1;
  TFRH(13) TFRH(15) TFRH(26) TFRH(6)   x0 += k1;  x1 += ks2 + 1u;
  TFRH(17) TFRH(29) TFRH(16) TFRH(24)  x0 += ks2; x1 += k0 + 2u;
  TFRH(13) TFRH(15) TFRH(26) TFRH(6)   x0 += k0;  x1 += k1 + 3u;
  TFRH(17) TFRH(29) TFRH(16) TFRH(24)  x0 += k1;  x1 += ks2 + 4u;
  TFRH(13) TFRH(15) TFRH(26) TFRH(6)   x0 += ks2; x1 += k0 + 5u;
#undef TFRH
  *o0 = x0; *o1 = x1;
}

static void compute_sel(Sel* S) {
  for (int i = 0; i < 2; i++) {
    unsigned kf0, kf1, a0, a1, b0, b1, c0, c1, d0, d1;
    tf_h(0u, 42u, 0u, (unsigned)i, &kf0, &kf1);
    tf_h(kf0, kf1, 0u, 2u, &a0, &a1);
    tf_h(kf0, kf1, 1u, 3u, &b0, &b1);
    unsigned kt0 = a1, kt1 = b1;
    tf_h(kt0, kt1, 0u, 2u, &c0, &c1);
    tf_h(kt0, kt1, 1u, 3u, &d0, &d1);
    unsigned sk0 = c1, sk1 = d1;
    (void)a0; (void)b0; (void)c0; (void)d0;
    unsigned keys[256];
    for (int j = 0; j < 128; j++) {
      unsigned y0, y1;
      tf_h(sk0, sk1, (unsigned)j, (unsigned)(j + 128), &y0, &y1);
      keys[j] = y0; keys[j + 128] = y1;
    }
    int perm[256];
    for (int t = 0; t < 256; t++) {
      unsigned my = keys[t];
      int rank = 0;
      for (int j = 0; j < 256; j++) {
        unsigned kj = keys[j];
        rank += (kj < my) || (kj == my && j < t);
      }
      perm[rank] = t;
    }
    if (i == 0) { for (int t = 0; t < 64;  t++) S->s0[t] = perm[t]; }
    else        { for (int t = 0; t < 128; t++) S->s1[t] = perm[t]; }
  }
}

extern "C" void kernel_launch(void* const* d_in, const int* in_sizes, int n_in,
                              void* d_out, int out_size) {
  const float* pred = (const float*)d_in[0];
  const float* f0   = (const float*)d_in[1];   // (32, 64, 128, 128)
  const float* f1   = (const float*)d_in[2];   // (32, 128, 64, 64)
  const float* f2   = (const float*)d_in[3];   // (32, 256, 32, 32)
  const int*   tgt  = (const int*)d_in[4];     // int32 (JAX x64 disabled)
  float* out = (float*)d_out;

  Sel sel;
  compute_sel(&sel);                            // deterministic constants

  k_passA<<<1824, 256>>>(pred, f0, f1, f2, tgt, sel);  // 1024 f0 + 512 f1 + 256 f2 + 32 main
  k_passB<<<897, 256>>>(f0, f1, f2, out);              // 128 f2 + 256 f1 + 512 f0 + final
}

// round 14
// speedup vs baseline: 1.0164x; 1.0164x over previous
#include <cuda_runtime.h>
#include <math.h>

#define FULLMASK 0xFFFFFFFFu

// ---------------- scratch (no allocations allowed) ----------------
__device__ double g_acc[8];            // 0..2 ifd0..2, 3..4 scr0..1
__device__ double g_main_part[32];
__device__ float  g_np0[32 * 32 * 64];   // norm partials [b][strip][c]
__device__ float  g_np1[32 * 16 * 128];
__device__ float  g_np2[32 * 8 * 256];
__device__ float  g_ps0[32 * 16384];     // per-pixel all-channel sums
__device__ float  g_ps1[32 * 4096];
__device__ float  g_ps2[32 * 1024];

struct Sel { int s0[64]; int s1[128]; };

__device__ __forceinline__ void warp_red(float& s) {
  for (int o = 16; o; o >>= 1) s += __shfl_down_sync(FULLMASK, s, o);
}

// fence-free: visibility to k_final is provided by the kernel boundary
__device__ __forceinline__ void block_add_double(float val, int slot, double* shd) {
  double d = (double)val;
  for (int o = 16; o; o >>= 1) d += __shfl_down_sync(FULLMASK, d, o);
  int t = threadIdx.x, w = t >> 5;
  if ((t & 31) == 0) shd[w] = d;
  __syncthreads();
  if (t == 0) {
    double s = 0.0;
    for (int i = 0; i < 8; i++) s += shd[i];
    atomicAdd(&g_acc[slot], s);
  }
}

// =========================== PASS A (reg-lean bodies) ===========================

// f0: block=(b, strip s of 512px = 4 rows of 128). 8 warps x 8 channels.
__device__ void passa_f0(float* buf, double* shd, const float* __restrict__ f0,
                         const float* __restrict__ f2, const Sel& sel, int b, int s) {
  int t = threadIdx.x, w = t >> 5, lane = t & 31;
  const float* base = f0 + (size_t)b * 64 * 16384 + s * 512;
  const float* tb = f2 + (size_t)b * 256 * 1024 + s * 32;  // texel row == s
  float4 ps[4];
#pragma unroll
  for (int q = 0; q < 4; q++) ps[q] = make_float4(0.f, 0.f, 0.f, 0.f);
  float scr = 0.f;
#pragma unroll
  for (int r = 0; r < 8; r++) {
    int c = w * 8 + r;
    const float4* pc = (const float4*)(base + (size_t)c * 16384);
    float tv = tb[(size_t)sel.s0[c] * 1024 + lane];
    float nn = 0.f;
#pragma unroll
    for (int q = 0; q < 4; q++) {
      float4 v = pc[lane + 32 * q];
      ps[q].x += v.x; ps[q].y += v.y; ps[q].z += v.z; ps[q].w += v.w;
      nn += v.x * v.x + v.y * v.y + v.z * v.z + v.w * v.w;
      float d0 = v.x - tv, d1 = v.y - tv, d2 = v.z - tv, d3 = v.w - tv;
      scr += d0 * d0 + d1 * d1 + d2 * d2 + d3 * d3;
    }
    warp_red(nn);                              // inline: frees n[] registers
    if (lane == 0) g_np0[((b * 32 + s) * 64) + c] = nn;
  }
  float4* b4 = (float4*)(buf + w * 512);
#pragma unroll
  for (int q = 0; q < 4; q++) b4[lane + 32 * q] = ps[q];
  __syncthreads();
  float* gp = g_ps0 + (size_t)b * 16384 + s * 512;
  for (int p = t; p < 512; p += 256) {
    float ss = 0.f;
#pragma unroll
    for (int w2 = 0; w2 < 8; w2++) ss += buf[w2 * 512 + p];
    gp[p] = ss;
  }
  block_add_double(scr, 3, shd);
}

// f1: block=(b, strip s of 256px = 4 rows of 64). 8 warps x 16 channels.
__device__ void passa_f1(float* buf, double* shd, const float* __restrict__ f1,
                         const float* __restrict__ f2, const Sel& sel, int b, int s) {
  int t = threadIdx.x, w = t >> 5, lane = t & 31;
  const float* base = f1 + (size_t)b * 128 * 4096 + s * 256;
  const float* tb = f2 + (size_t)b * 256 * 1024;
  int tcol = (2 * lane) & 31;
  float4 ps0 = make_float4(0.f, 0.f, 0.f, 0.f), ps1 = ps0;
  float scr = 0.f;
#pragma unroll
  for (int r = 0; r < 16; r++) {
    int c = w * 16 + r;
    const float4* pc = (const float4*)(base + (size_t)c * 4096);
    const float* tc = tb + (size_t)sel.s1[c] * 1024;
    float2 t0 = *(const float2*)(tc + (2 * s) * 32 + tcol);
    float2 t1 = *(const float2*)(tc + (2 * s + 1) * 32 + tcol);
    float4 v0 = pc[lane];
    float4 v1 = pc[lane + 32];
    ps0.x += v0.x; ps0.y += v0.y; ps0.z += v0.z; ps0.w += v0.w;
    ps1.x += v1.x; ps1.y += v1.y; ps1.z += v1.z; ps1.w += v1.w;
    float nn = v0.x * v0.x + v0.y * v0.y + v0.z * v0.z + v0.w * v0.w
             + v1.x * v1.x + v1.y * v1.y + v1.z * v1.z + v1.w * v1.w;
    float a0 = v0.x - t0.x, a1 = v0.y - t0.x, a2 = v0.z - t0.y, a3 = v0.w - t0.y;
    float b0 = v1.x - t1.x, b1 = v1.y - t1.x, b2 = v1.z - t1.y, b3 = v1.w - t1.y;
    scr += a0 * a0 + a1 * a1 + a2 * a2 + a3 * a3
         + b0 * b0 + b1 * b1 + b2 * b2 + b3 * b3;
    warp_red(nn);
    if (lane == 0) g_np1[((b * 16 + s) * 128) + c] = nn;
  }
  float4* b4 = (float4*)(buf + w * 256);
  b4[lane] = ps0;
  b4[lane + 32] = ps1;
  __syncthreads();
  float* gp = g_ps1 + (size_t)b * 4096 + s * 256;
  if (t < 256) {
    float ss = 0.f;
#pragma unroll
    for (int w2 = 0; w2 < 8; w2++) ss += buf[w2 * 256 + t];
    gp[t] = ss;
  }
  block_add_double(scr, 4, shd);
}

// f2: block=(b, strip s of 128px). 8 warps x 32 channels. no teacher.
__device__ void passa_f2(float* buf, const float* __restrict__ f2, int b, int s) {
  int t = threadIdx.x, w = t >> 5, lane = t & 31;
  const float* base = f2 + (size_t)b * 256 * 1024 + s * 128;
  float4 ps = make_float4(0.f, 0.f, 0.f, 0.f);
#pragma unroll
  for (int g = 0; g < 4; g++) {
#pragma unroll
    for (int r = 0; r < 8; r++) {
      int c = w * 32 + g * 8 + r;
      float4 v = ((const float4*)(base + (size_t)c * 1024))[lane];
      ps.x += v.x; ps.y += v.y; ps.z += v.z; ps.w += v.w;
      float nn = v.x * v.x + v.y * v.y + v.z * v.z + v.w * v.w;
      warp_red(nn);
      if (lane == 0) g_np2[((b * 8 + s) * 256) + c] = nn;
    }
  }
  float4* b4 = (float4*)(buf + w * 128);
  b4[lane] = ps;
  __syncthreads();
  float* gp = g_ps2 + (size_t)b * 1024 + s * 128;
  if (t < 128) {
    float ss = 0.f;
#pragma unroll
    for (int w2 = 0; w2 < 8; w2++) ss += buf[w2 * 128 + t];
    gp[t] = ss;
  }
}

// l_main
__device__ void main_body(const float* __restrict__ pred, const int* __restrict__ tgt, int b) {
  __shared__ float sh[8];
  __shared__ float shm;
  int t = threadIdx.x;
  const float* row = pred + b * 1000;
  float m = -1e30f;
  for (int i = t; i < 1000; i += 256) m = fmaxf(m, row[i]);
  for (int o = 16; o; o >>= 1) m = fmaxf(m, __shfl_down_sync(FULLMASK, m, o));
  if ((t & 31) == 0) sh[t >> 5] = m;
  __syncthreads();
  if (t == 0) {
    float mm = sh[0];
    for (int i = 1; i < 8; i++) mm = fmaxf(mm, sh[i]);
    shm = mm;
  }
  __syncthreads();
  m = shm;
  float s = 0.f;
  for (int i = t; i < 1000; i += 256) s += expf(row[i] - m);
  for (int o = 16; o; o >>= 1) s += __shfl_down_sync(FULLMASK, s, o);
  if ((t & 31) == 0) sh[t >> 5] = s;
  __syncthreads();
  if (t == 0) {
    float ss = 0.f;
    for (int i = 0; i < 8; i++) ss += sh[i];
    int tg = tgt[b];
    double lp = (double)(row[tg] - m) - log((double)ss);
    g_main_part[b] = -lp;
  }
}

__global__ void __launch_bounds__(256, 5) k_passA(
    const float* __restrict__ pred, const float* __restrict__ f0,
    const float* __restrict__ f1, const float* __restrict__ f2,
    const int* __restrict__ tgt, Sel sel) {
  __shared__ __align__(16) float buf[8 * 512];
  __shared__ double shd[8];
  int bid = blockIdx.x;
  if (bid < 1024) { passa_f0(buf, shd, f0, f2, sel, bid >> 5, bid & 31); return; }
  bid -= 1024;
  if (bid < 512)  { passa_f1(buf, shd, f1, f2, sel, bid >> 4, bid & 15); return; }
  bid -= 512;
  if (bid < 256)  { passa_f2(buf, f2, bid >> 3, bid & 7); return; }
  bid -= 256;
  main_body(pred, tgt, bid);
}

// =========================== PASS B (R10 exact, fence-free) ===========================

template <int C>
__device__ __forceinline__ void rank_strong(const float* ns, int* sidx) {
  int t = threadIdx.x;
  if (t < C) {
    float v = ns[t];
    int rank = 0;
#pragma unroll 4
    for (int j = 0; j < C; j++) {
      float nj = ns[j];
      rank += (nj > v) || (nj == v && j < t);   // argsort(-norm), stable
    }
    if (rank < C / 2) sidx[rank] = t;
  }
  __syncthreads();
}

__device__ __forceinline__ float sigmoidf_(float x) { return 1.f / (1.f + expf(-x)); }

// f0: 16 blocks/batch, vec4 (1024 px/block), 32 strong planes
__device__ void passb_f0(const float* __restrict__ f0, int b, int pb,
                         float* ns, int* sidx, double* shd) {
  int t = threadIdx.x;
  if (t < 64) {
    float s = 0.f;
    const float* pp = g_np0 + b * 32 * 64 + t;
#pragma unroll 8
    for (int k = 0; k < 32; k++) s += pp[k * 64];
    ns[t] = s;
  }
  __syncthreads();
  rank_strong<64>(ns, sidx);
  int p0 = pb * 1024 + t * 4;
  const float* xb = f0 + (size_t)b * 64 * 16384 + p0;
  float s0 = 0.f, s1 = 0.f, s2 = 0.f, s3 = 0.f;
#pragma unroll 8
  for (int k = 0; k < 32; k++) {
    float4 v = *(const float4*)(xb + (size_t)sidx[k] * 16384);
    s0 += v.x; s1 += v.y; s2 += v.z; s3 += v.w;
  }
  float4 pa = *(const float4*)(g_ps0 + (size_t)b * 16384 + p0);
  const float inv = 1.f / 32.f;
  float d0 = sigmoidf_((pa.x - s0) * inv) - sigmoidf_(s0 * inv);
  float d1 = sigmoidf_((pa.y - s1) * inv) - sigmoidf_(s1 * inv);
  float d2 = sigmoidf_((pa.z - s2) * inv) - sigmoidf_(s2 * inv);
  float d3 = sigmoidf_((pa.w - s3) * inv) - sigmoidf_(s3 * inv);
  block_add_double(d0 * d0 + d1 * d1 + d2 * d2 + d3 * d3, 0, shd);
}

// f1: 8 blocks/batch, vec2 (512 px/block), 64 strong planes
__device__ void passb_f1(const float* __restrict__ f1, int b, int pb,
                         float* ns, int* sidx, double* shd) {
  int t = threadIdx.x;
  if (t < 128) {
    float s = 0.f;
    const float* pp = g_np1 + b * 16 * 128 + t;
#pragma unroll 8
    for (int k = 0; k < 16; k++) s += pp[k * 128];
    ns[t] = s;
  }
  __syncthreads();
  rank_strong<128>(ns, sidx);
  int p0 = pb * 512 + t * 2;
  const float* xb = f1 + (size_t)b * 128 * 4096 + p0;
  float s0 = 0.f, s1 = 0.f;
#pragma unroll 8
  for (int k = 0; k < 64; k++) {
    float2 v = *(const float2*)(xb + (size_t)sidx[k] * 4096);
    s0 += v.x; s1 += v.y;
  }
  float2 pa = *(const float2*)(g_ps1 + (size_t)b * 4096 + p0);
  const float inv = 1.f / 64.f;
  float d0 = sigmoidf_((pa.x - s0) * inv) - sigmoidf_(s0 * inv);
  float d1 = sigmoidf_((pa.y - s1) * inv) - sigmoidf_(s1 * inv);
  block_add_double(d0 * d0 + d1 * d1, 1, shd);
}

// f2: 4 blocks/batch, vec1 (256 px/block), 128 strong planes
__device__ void passb_f2(const float* __restrict__ f2, int b, int pb,
                         float* ns, int* sidx, double* shd) {
  int t = threadIdx.x;
  {
    float s = 0.f;
    const float* pp = g_np2 + b * 8 * 256 + t;
#pragma unroll 8
    for (int k = 0; k < 8; k++) s += pp[k * 256];
    ns[t] = s;
  }
  __syncthreads();
  rank_strong<256>(ns, sidx);
  int p0 = pb * 256 + t;
  const float* xb = f2 + (size_t)b * 256 * 1024 + p0;
  float s0 = 0.f;
#pragma unroll 8
  for (int k = 0; k < 128; k++) {
    s0 += xb[(size_t)sidx[k] * 1024];
  }
  float pa = g_ps2[(size_t)b * 1024 + p0];
  const float inv = 1.f / 128.f;
  float d0 = sigmoidf_((pa - s0) * inv) - sigmoidf_(s0 * inv);
  block_add_double(d0 * d0, 2, shd);
}

__global__ void __launch_bounds__(256) k_passB(
    const float* __restrict__ f0, const float* __restrict__ f1,
    const float* __restrict__ f2) {
  __shared__ float ns[256];
  __shared__ int sidx[128];
  __shared__ double shd[8];
  int bid = blockIdx.x;
  // f2 first (still warm in L2 from passA), then f1, then f0
  if (bid < 128) { passb_f2(f2, bid >> 2, bid & 3, ns, sidx, shd); return; }
  bid -= 128;
  if (bid < 256) { passb_f1(f1, bid >> 3, bid & 7, ns, sidx, shd); return; }
  bid -= 256;
  passb_f0(f0, bid >> 4, bid & 15, ns, sidx, shd);
}

// =========================== FINAL (separate launch) ===========================
__global__ void k_final(float* __restrict__ out) {
  if (threadIdx.x == 0) {
    double lm = 0.0;
    for (int i = 0; i < 32; i++) lm += g_main_part[i];
    double l_main = lm / 32.0;
    double ifd0 = g_acc[0] / (32.0 * 128.0 * 128.0);
    double ifd1 = g_acc[1] / (32.0 * 64.0 * 64.0);
    double ifd2 = g_acc[2] / (32.0 * 32.0 * 32.0);
    double l_ifd = (ifd0 + ifd1 + ifd2) / 3.0;
    double scr0 = g_acc[3] / (32.0 * 64.0 * 128.0 * 128.0);
    double scr1 = g_acc[4] / (32.0 * 128.0 * 64.0 * 64.0);
    double l_scr = (scr0 + scr1) / 2.0;
    double total = l_main + 0.015 * l_scr + 0.015 * l_ifd;
    out[0] = (float)total;
    out[1] = (float)l_main;
    out[2] = (float)l_scr;
    out[3] = (float)l_ifd;
    for (int i = 0; i < 8; i++) g_acc[i] = 0.0;   // reset for next replay
  }
}

// =========================== HOST: constant channel permutations ===========================
static void tf_h(unsigned k0, unsigned k1, unsigned x0, unsigned x1,
                 unsigned* o0, unsigned* o1) {
  unsigned ks2 = 0x1BD11BDAu ^ k0 ^ k1;
#define TFRH(r) { x0 += x1; x1 = (x1 << (r)) | (x1 >> (32 - (r))); x1 ^= x0; }
  x0 += k0; x1 += k1;
  TFRH(13) TFRH(15) TFRH(26) TFRH(6)   x0 += k1;  x1 += ks2 + 1u;
  TFRH(17) TFRH(29) TFRH(16) TFRH(24)  x0 += ks2; x1 += k0 + 2u;
  TFRH(13) TFRH(15) TFRH(26) TFRH(6)   x0 += k0;  x1 += k1 + 3u;
  TFRH(17) TFRH(29) TFRH(16) TFRH(24)  x0 += k1;  x1 += ks2 + 4u;
  TFRH(13) TFRH(15) TFRH(26) TFRH(6)   x0 += ks2; x1 += k0 + 5u;
#undef TFRH
  *o0 = x0; *o1 = x1;
}

static void compute_sel(Sel* S) {
  for (int i = 0; i < 2; i++) {
    unsigned kf0, kf1, a0, a1, b0, b1, c0, c1, d0, d1;
    tf_h(0u, 42u, 0u, (unsigned)i, &kf0, &kf1);
    tf_h(kf0, kf1, 0u, 2u, &a0, &a1);
    tf_h(kf0, kf1, 1u, 3u, &b0, &b1);
    unsigned kt0 = a1, kt1 = b1;
    tf_h(kt0, kt1, 0u, 2u, &c0, &c1);
    tf_h(kt0, kt1, 1u, 3u, &d0, &d1);
    unsigned sk0 = c1, sk1 = d1;
    (void)a0; (void)b0; (void)c0; (void)d0;
    unsigned keys[256];
    for (int j = 0; j < 128; j++) {
      unsigned y0, y1;
      tf_h(sk0, sk1, (unsigned)j, (unsigned)(j + 128), &y0, &y1);
      keys[j] = y0; keys[j + 128] = y1;
    }
    int perm[256];
    for (int t = 0; t < 256; t++) {
      unsigned my = keys[t];
      int rank = 0;
      for (int j = 0; j < 256; j++) {
        unsigned kj = keys[j];
        rank += (kj < my) || (kj == my && j < t);
      }
      perm[rank] = t;
    }
    if (i == 0) { for (int t = 0; t < 64;  t++) S->s0[t] = perm[t]; }
    else        { for (int t = 0; t < 128; t++) S->s1[t] = perm[t]; }
  }
}

extern "C" void kernel_launch(void* const* d_in, const int* in_sizes, int n_in,
                              void* d_out, int out_size) {
  const float* pred = (const float*)d_in[0];
  const float* f0   = (const float*)d_in[1];   // (32, 64, 128, 128)
  const float* f1   = (const float*)d_in[2];   // (32, 128, 64, 64)
  const float* f2   = (const float*)d_in[3];   // (32, 256, 32, 32)
  const int*   tgt  = (const int*)d_in[4];     // int32 (JAX x64 disabled)
  float* out = (float*)d_out;

  Sel sel;
  compute_sel(&sel);                            // deterministic constants

  k_passA<<<1824, 256>>>(pred, f0, f1, f2, tgt, sel);  // 1024 f0 + 512 f1 + 256 f2 + 32 main
  k_passB<<<896, 256>>>(f0, f1, f2);                   // 128 f2 + 256 f1 + 512 f0
  k_final<<<1, 32>>>(out);
}

// round 15
// speedup vs baseline: 1.0807x; 1.0633x over previous
#include <cuda_runtime.h>
#include <math.h>

#define FULLMASK 0xFFFFFFFFu

// ---------------- scratch (no allocations allowed) ----------------
__device__ double g_acc[8];            // 0..2 ifd0..2, 3..4 scr0..1
__device__ double g_main_part[32];
__device__ float  g_np0[32 * 32 * 64];   // norm partials [b][strip][c]
__device__ float  g_np1[32 * 16 * 128];
__device__ float  g_np2[32 * 8 * 256];
__device__ float  g_ps0[32 * 16384];     // per-pixel all-channel sums
__device__ float  g_ps1[32 * 4096];

struct Sel { int s0[64]; int s1[128]; };

__device__ __forceinline__ void warp_red(float& s) {
  for (int o = 16; o; o >>= 1) s += __shfl_down_sync(FULLMASK, s, o);
}

// fence-free: visibility to later kernels via kernel boundary
__device__ __forceinline__ void block_add_double(float val, int slot, double* shd) {
  double d = (double)val;
  for (int o = 16; o; o >>= 1) d += __shfl_down_sync(FULLMASK, d, o);
  int t = threadIdx.x, w = t >> 5;
  if ((t & 31) == 0) shd[w] = d;
  __syncthreads();
  if (t == 0) {
    double s = 0.0;
    for (int i = 0; i < 8; i++) s += shd[i];
    atomicAdd(&g_acc[slot], s);
  }
}

// =========================== K0: f2 norms + l_main ===========================

// f2 norms: block=(b, strip s of 128px). 8 warps x 32 channels. (R10 structure)
__device__ void k0_f2norm(const float* __restrict__ f2, int b, int s) {
  int w = threadIdx.x >> 5, lane = threadIdx.x & 31;
  const float* base = f2 + (size_t)b * 256 * 1024 + s * 128;
#pragma unroll
  for (int g = 0; g < 4; g++) {
    float n[8];
#pragma unroll
    for (int r = 0; r < 8; r++) {
      int c = w * 32 + g * 8 + r;
      float4 v = ((const float4*)(base + (size_t)c * 1024))[lane];
      n[r] = v.x * v.x + v.y * v.y + v.z * v.z + v.w * v.w;
    }
#pragma unroll
    for (int r = 0; r < 8; r++) {
      float nn = n[r];
      warp_red(nn);
      if (lane == 0) g_np2[((b * 8 + s) * 256) + w * 32 + g * 8 + r] = nn;
    }
  }
}

// l_main
__device__ void main_body(const float* __restrict__ pred, const int* __restrict__ tgt, int b) {
  __shared__ float sh[8];
  __shared__ float shm;
  int t = threadIdx.x;
  const float* row = pred + b * 1000;
  float m = -1e30f;
  for (int i = t; i < 1000; i += 256) m = fmaxf(m, row[i]);
  for (int o = 16; o; o >>= 1) m = fmaxf(m, __shfl_down_sync(FULLMASK, m, o));
  if ((t & 31) == 0) sh[t >> 5] = m;
  __syncthreads();
  if (t == 0) {
    float mm = sh[0];
    for (int i = 1; i < 8; i++) mm = fmaxf(mm, sh[i]);
    shm = mm;
  }
  __syncthreads();
  m = shm;
  float s = 0.f;
  for (int i = t; i < 1000; i += 256) s += expf(row[i] - m);
  for (int o = 16; o; o >>= 1) s += __shfl_down_sync(FULLMASK, s, o);
  if ((t & 31) == 0) sh[t >> 5] = s;
  __syncthreads();
  if (t == 0) {
    float ss = 0.f;
    for (int i = 0; i < 8; i++) ss += sh[i];
    int tg = tgt[b];
    double lp = (double)(row[tg] - m) - log((double)ss);
    g_main_part[b] = -lp;
  }
}

__global__ void __launch_bounds__(256) k_pass0(
    const float* __restrict__ pred, const float* __restrict__ f2,
    const int* __restrict__ tgt) {
  int bid = blockIdx.x;
  if (bid < 256) { k0_f2norm(f2, bid >> 3, bid & 7); return; }
  main_body(pred, tgt, bid - 256);
}

// =========================== shared ranking helpers ===========================

template <int C>
__device__ __forceinline__ void rank_strong(const float* ns, int* sidx) {
  int t = threadIdx.x;
  if (t < C) {
    float v = ns[t];
    int rank = 0;
#pragma unroll 4
    for (int j = 0; j < C; j++) {
      float nj = ns[j];
      rank += (nj > v) || (nj == v && j < t);   // argsort(-norm), stable
    }
    if (rank < C / 2) sidx[rank] = t;
  }
  __syncthreads();
}

template <int C>
__device__ __forceinline__ void rank_flags(const float* ns, unsigned char* fl) {
  int t = threadIdx.x;
  if (t < C) {
    float v = ns[t];
    int rank = 0;
#pragma unroll 4
    for (int j = 0; j < C; j++) {
      float nj = ns[j];
      rank += (nj > v) || (nj == v && j < t);
    }
    fl[t] = (rank < C / 2) ? (unsigned char)0 : (unsigned char)1;
  }
  __syncthreads();
}

__device__ __forceinline__ float sigmoidf_(float x) { return 1.f / (1.f + expf(-x)); }

// =========================== PASS A (R10 bodies + __ldcs; f2 IFD inline) ===========

// f0: block=(b, strip s of 512px). 8 warps x 8 channels. (R10 exact + __ldcs)
__device__ void passa_f0(float* buf, double* shd, const float* __restrict__ f0,
                         const float* __restrict__ f2, const Sel& sel, int b, int s) {
  int t = threadIdx.x, w = t >> 5, lane = t & 31;
  const float* base = f0 + (size_t)b * 64 * 16384 + s * 512;
  const float* tb = f2 + (size_t)b * 256 * 1024 + s * 32;  // texel row == s
  float4 ps[4];
#pragma unroll
  for (int q = 0; q < 4; q++) ps[q] = make_float4(0.f, 0.f, 0.f, 0.f);
  float n[8];
  float scr = 0.f;
#pragma unroll
  for (int r = 0; r < 8; r++) {
    int c = w * 8 + r;
    const float4* pc = (const float4*)(base + (size_t)c * 16384);
    float tv = tb[(size_t)sel.s0[c] * 1024 + lane];
    float nn = 0.f;
#pragma unroll
    for (int q = 0; q < 4; q++) {
      float4 v = __ldcs(pc + lane + 32 * q);    // evict-first: protect f2 in L2
      ps[q].x += v.x; ps[q].y += v.y; ps[q].z += v.z; ps[q].w += v.w;
      nn += v.x * v.x + v.y * v.y + v.z * v.z + v.w * v.w;
      float d0 = v.x - tv, d1 = v.y - tv, d2 = v.z - tv, d3 = v.w - tv;
      scr += d0 * d0 + d1 * d1 + d2 * d2 + d3 * d3;
    }
    n[r] = nn;
  }
#pragma unroll
  for (int r = 0; r < 8; r++) {
    float nn = n[r];
    warp_red(nn);
    if (lane == 0) g_np0[((b * 32 + s) * 64) + w * 8 + r] = nn;
  }
  float4* b4 = (float4*)(buf + w * 512);
#pragma unroll
  for (int q = 0; q < 4; q++) b4[lane + 32 * q] = ps[q];
  __syncthreads();
  float* gp = g_ps0 + (size_t)b * 16384 + s * 512;
  for (int p = t; p < 512; p += 256) {
    float ss = 0.f;
#pragma unroll
    for (int w2 = 0; w2 < 8; w2++) ss += buf[w2 * 512 + p];
    gp[p] = ss;
  }
  block_add_double(scr, 3, shd);
}

// f1: block=(b, strip s of 256px). 8 warps x 16 channels. (R10 exact + __ldcs)
__device__ void passa_f1(float* buf, double* shd, const float* __restrict__ f1,
                         const float* __restrict__ f2, const Sel& sel, int b, int s) {
  int t = threadIdx.x, w = t >> 5, lane = t & 31;
  const float* base = f1 + (size_t)b * 128 * 4096 + s * 256;
  const float* tb = f2 + (size_t)b * 256 * 1024;
  int tcol = (2 * lane) & 31;
  float4 ps0 = make_float4(0.f, 0.f, 0.f, 0.f), ps1 = ps0;
  float n[16];
  float scr = 0.f;
#pragma unroll
  for (int r = 0; r < 16; r++) {
    int c = w * 16 + r;
    const float4* pc = (const float4*)(base + (size_t)c * 4096);
    const float* tc = tb + (size_t)sel.s1[c] * 1024;
    float2 t0 = *(const float2*)(tc + (2 * s) * 32 + tcol);
    float2 t1 = *(const float2*)(tc + (2 * s + 1) * 32 + tcol);
    float4 v0 = __ldcs(pc + lane);
    float4 v1 = __ldcs(pc + lane + 32);
    ps0.x += v0.x; ps0.y += v0.y; ps0.z += v0.z; ps0.w += v0.w;
    ps1.x += v1.x; ps1.y += v1.y; ps1.z += v1.z; ps1.w += v1.w;
    n[r] = v0.x * v0.x + v0.y * v0.y + v0.z * v0.z + v0.w * v0.w
         + v1.x * v1.x + v1.y * v1.y + v1.z * v1.z + v1.w * v1.w;
    float a0 = v0.x - t0.x, a1 = v0.y - t0.x, a2 = v0.z - t0.y, a3 = v0.w - t0.y;
    float b0 = v1.x - t1.x, b1 = v1.y - t1.x, b2 = v1.z - t1.y, b3 = v1.w - t1.y;
    scr += a0 * a0 + a1 * a1 + a2 * a2 + a3 * a3
         + b0 * b0 + b1 * b1 + b2 * b2 + b3 * b3;
  }
#pragma unroll
  for (int r = 0; r < 16; r++) {
    float nn = n[r];
    warp_red(nn);
    if (lane == 0) g_np1[((b * 16 + s) * 128) + w * 16 + r] = nn;
  }
  float4* b4 = (float4*)(buf + w * 256);
  b4[lane] = ps0;
  b4[lane + 32] = ps1;
  __syncthreads();
  float* gp = g_ps1 + (size_t)b * 4096 + s * 256;
  if (t < 256) {
    float ss = 0.f;
#pragma unroll
    for (int w2 = 0; w2 < 8; w2++) ss += buf[w2 * 256 + t];
    gp[t] = ss;
  }
  block_add_double(scr, 4, shd);
}

// f2 IFD inline: block=(b, strip s of 128px). 8 warps x 32 channels.
// Norms (g_np2 from K0) -> flags; one read of f2 (L2-warm) gives strong+total.
__device__ void passa_f2ifd(float* buf, double* shd, const float* __restrict__ f2,
                            float* ns, unsigned char* fl, int b, int s) {
  int t = threadIdx.x, w = t >> 5, lane = t & 31;
  {
    float acc = 0.f;
    const float* pp = g_np2 + b * 8 * 256 + t;
#pragma unroll 8
    for (int k = 0; k < 8; k++) acc += pp[k * 256];
    ns[t] = acc;
  }
  __syncthreads();
  rank_flags<256>(ns, fl);

  const float* base = f2 + (size_t)b * 256 * 1024 + s * 128;
  float4 st = make_float4(0.f, 0.f, 0.f, 0.f);
  float4 tt = st;
#pragma unroll 8
  for (int g = 0; g < 32; g++) {
    int c = w * 32 + g;
    float4 v = ((const float4*)(base + (size_t)c * 1024))[lane];
    tt.x += v.x; tt.y += v.y; tt.z += v.z; tt.w += v.w;
    if (!fl[c]) { st.x += v.x; st.y += v.y; st.z += v.z; st.w += v.w; }
  }
  // stage per-warp partials: bufS[w][128], bufT[w][128]
  float* bufS = buf;
  float* bufT = buf + 1024;
  *(float4*)(bufS + w * 128 + lane * 4) = st;
  *(float4*)(bufT + w * 128 + lane * 4) = tt;
  __syncthreads();
  float ifd = 0.f;
  if (t < 128) {
    float sS = 0.f, sT = 0.f;
#pragma unroll
    for (int w2 = 0; w2 < 8; w2++) {
      sS += bufS[w2 * 128 + t];
      sT += bufT[w2 * 128 + t];
    }
    const float inv = 1.f / 128.f;
    float d = sigmoidf_((sT - sS) * inv) - sigmoidf_(sS * inv);
    ifd = d * d;
  }
  block_add_double(ifd, 2, shd);
}

__global__ void __launch_bounds__(256) k_passA(
    const float* __restrict__ f0, const float* __restrict__ f1,
    const float* __restrict__ f2, Sel sel) {
  __shared__ __align__(16) float buf[8 * 512];
  __shared__ double shd[8];
  __shared__ float ns[256];
  __shared__ unsigned char fl[256];
  int bid = blockIdx.x;
  // f2 IFD first: f2 is L2-warm from K0
  if (bid < 256)  { passa_f2ifd(buf, shd, f2, ns, fl, bid >> 3, bid & 7); return; }
  bid -= 256;
  if (bid < 1024) { passa_f0(buf, shd, f0, f2, sel, bid >> 5, bid & 31); return; }
  bid -= 1024;
  passa_f1(buf, shd, f1, f2, sel, bid >> 4, bid & 15);
}

// =========================== PASS B (R10 exact, f0/f1 only) ===========================

// f0: 16 blocks/batch, vec4 (1024 px/block), 32 strong planes
__device__ void passb_f0(const float* __restrict__ f0, int b, int pb,
                         float* ns, int* sidx, double* shd) {
  int t = threadIdx.x;
  if (t < 64) {
    float s = 0.f;
    const float* pp = g_np0 + b * 32 * 64 + t;
#pragma unroll 8
    for (int k = 0; k < 32; k++) s += pp[k * 64];
    ns[t] = s;
  }
  __syncthreads();
  rank_strong<64>(ns, sidx);
  int p0 = pb * 1024 + t * 4;
  const float* xb = f0 + (size_t)b * 64 * 16384 + p0;
  float s0 = 0.f, s1 = 0.f, s2 = 0.f, s3 = 0.f;
#pragma unroll 8
  for (int k = 0; k < 32; k++) {
    float4 v = *(const float4*)(xb + (size_t)sidx[k] * 16384);
    s0 += v.x; s1 += v.y; s2 += v.z; s3 += v.w;
  }
  float4 pa = *(const float4*)(g_ps0 + (size_t)b * 16384 + p0);
  const float inv = 1.f / 32.f;
  float d0 = sigmoidf_((pa.x - s0) * inv) - sigmoidf_(s0 * inv);
  float d1 = sigmoidf_((pa.y - s1) * inv) - sigmoidf_(s1 * inv);
  float d2 = sigmoidf_((pa.z - s2) * inv) - sigmoidf_(s2 * inv);
  float d3 = sigmoidf_((pa.w - s3) * inv) - sigmoidf_(s3 * inv);
  block_add_double(d0 * d0 + d1 * d1 + d2 * d2 + d3 * d3, 0, shd);
}

// f1: 8 blocks/batch, vec2 (512 px/block), 64 strong planes
__device__ void passb_f1(const float* __restrict__ f1, int b, int pb,
                         float* ns, int* sidx, double* shd) {
  int t = threadIdx.x;
  if (t < 128) {
    float s = 0.f;
    const float* pp = g_np1 + b * 16 * 128 + t;
#pragma unroll 8
    for (int k = 0; k < 16; k++) s += pp[k * 128];
    ns[t] = s;
  }
  __syncthreads();
  rank_strong<128>(ns, sidx);
  int p0 = pb * 512 + t * 2;
  const float* xb = f1 + (size_t)b * 128 * 4096 + p0;
  float s0 = 0.f, s1 = 0.f;
#pragma unroll 8
  for (int k = 0; k < 64; k++) {
    float2 v = *(const float2*)(xb + (size_t)sidx[k] * 4096);
    s0 += v.x; s1 += v.y;
  }
  float2 pa = *(const float2*)(g_ps1 + (size_t)b * 4096 + p0);
  const float inv = 1.f / 64.f;
  float d0 = sigmoidf_((pa.x - s0) * inv) - sigmoidf_(s0 * inv);
  float d1 = sigmoidf_((pa.y - s1) * inv) - sigmoidf_(s1 * inv);
  block_add_double(d0 * d0 + d1 * d1, 1, shd);
}

__global__ void __launch_bounds__(256) k_passB(
    const float* __restrict__ f0, const float* __restrict__ f1) {
  __shared__ float ns[256];
  __shared__ int sidx[128];
  __shared__ double shd[8];
  int bid = blockIdx.x;
  if (bid < 256) { passb_f1(f1, bid >> 3, bid & 7, ns, sidx, shd); return; }
  bid -= 256;
  passb_f0(f0, bid >> 4, bid & 15, ns, sidx, shd);
}

// =========================== FINAL ===========================
__global__ void k_final(float* __restrict__ out) {
  if (threadIdx.x == 0) {
    double lm = 0.0;
    for (int i = 0; i < 32; i++) lm += g_main_part[i];
    double l_main = lm / 32.0;
    double ifd0 = g_acc[0] / (32.0 * 128.0 * 128.0);
    double ifd1 = g_acc[1] / (32.0 * 64.0 * 64.0);
    double ifd2 = g_acc[2] / (32.0 * 32.0 * 32.0);
    double l_ifd = (ifd0 + ifd1 + ifd2) / 3.0;
    double scr0 = g_acc[3] / (32.0 * 64.0 * 128.0 * 128.0);
    double scr1 = g_acc[4] / (32.0 * 128.0 * 64.0 * 64.0);
    double l_scr = (scr0 + scr1) / 2.0;
    double total = l_main + 0.015 * l_scr + 0.015 * l_ifd;
    out[0] = (float)total;
    out[1] = (float)l_main;
    out[2] = (float)l_scr;
    out[3] = (float)l_ifd;
    for (int i = 0; i < 8; i++) g_acc[i] = 0.0;   // reset for next replay
  }
}

// =========================== HOST: constant channel permutations ===========================
static void tf_h(unsigned k0, unsigned k1, unsigned x0, unsigned x1,
                 unsigned* o0, unsigned* o1) {
  unsigned ks2 = 0x1BD11BDAu ^ k0 ^ k1;
#define TFRH(r) { x0 += x1; x1 = (x1 << (r)) | (x1 >> (32 - (r))); x1 ^= x0; }
  x0 += k0; x1 += k1;
  TFRH(13) TFRH(15) TFRH(26) TFRH(6)   x0 += k1;  x1 += ks2 + 1u;
  TFRH(17) TFRH(29) TFRH(16) TFRH(24)  x0 += ks2; x1 += k0 + 2u;
  TFRH(13) TFRH(15) TFRH(26) TFRH(6)   x0 += k0;  x1 += k1 + 3u;
  TFRH(17) TFRH(29) TFRH(16) TFRH(24)  x0 += k1;  x1 += ks2 + 4u;
  TFRH(13) TFRH(15) TFRH(26) TFRH(6)   x0 += ks2; x1 += k0 + 5u;
#undef TFRH
  *o0 = x0; *o1 = x1;
}

static void compute_sel(Sel* S) {
  for (int i = 0; i < 2; i++) {
    unsigned kf0, kf1, a0, a1, b0, b1, c0, c1, d0, d1;
    tf_h(0u, 42u, 0u, (unsigned)i, &kf0, &kf1);
    tf_h(kf0, kf1, 0u, 2u, &a0, &a1);
    tf_h(kf0, kf1, 1u, 3u, &b0, &b1);
    unsigned kt0 = a1, kt1 = b1;
    tf_h(kt0, kt1, 0u, 2u, &c0, &c1);
    tf_h(kt0, kt1, 1u, 3u, &d0, &d1);
    unsigned sk0 = c1, sk1 = d1;
    (void)a0; (void)b0; (void)c0; (void)d0;
    unsigned keys[256];
    for (int j = 0; j < 128; j++) {
      unsigned y0, y1;
      tf_h(sk0, sk1, (unsigned)j, (unsigned)(j + 128), &y0, &y1);
      keys[j] = y0; keys[j + 128] = y1;
    }
    int perm[256];
    for (int t = 0; t < 256; t++) {
      unsigned my = keys[t];
      int rank = 0;
      for (int j = 0; j < 256; j++) {
        unsigned kj = keys[j];
        rank += (kj < my) || (kj == my && j < t);
      }
      perm[rank] = t;
    }
    if (i == 0) { for (int t = 0; t < 64;  t++) S->s0[t] = perm[t]; }
    else        { for (int t = 0; t < 128; t++) S->s1[t] = perm[t]; }
  }
}

extern "C" void kernel_launch(void* const* d_in, const int* in_sizes, int n_in,
                              void* d_out, int out_size) {
  const float* pred = (const float*)d_in[0];
  const float* f0   = (const float*)d_in[1];   // (32, 64, 128, 128)
  const float* f1   = (const float*)d_in[2];   // (32, 128, 64, 64)
  const float* f2   = (const float*)d_in[3];   // (32, 256, 32, 32)
  const int*   tgt  = (const int*)d_in[4];     // int32 (JAX x64 disabled)
  float* out = (float*)d_out;

  Sel sel;
  compute_sel(&sel);                            // deterministic constants

  k_pass0<<<288, 256>>>(pred, f2, tgt);         // 256 f2norm + 32 main; warms L2 with f2
  k_passA<<<1792, 256>>>(f0, f1, f2, sel);      // 256 f2ifd + 1024 f0 + 512 f1
  k_passB<<<768, 256>>>(f0, f1);                // 256 f1 + 512 f0
  k_final<<<1, 32>>>(out);
}

// round 16
// speedup vs baseline: 1.1125x; 1.0294x over previous
#include <cuda_runtime.h>
#include <math.h>

#define FULLMASK 0xFFFFFFFFu

// ---------------- scratch (no allocations allowed) ----------------
__device__ double g_acc[8];            // 0..2 ifd0..2, 3..4 scr0..1
__device__ double g_main_part[32];
__device__ float  g_np0[32 * 32 * 64];   // norm partials [b][strip][c]
__device__ float  g_np1[32 * 16 * 128];
__device__ float  g_np2[32 * 8 * 256];
__device__ float  g_ps0[32 * 16384];     // per-pixel all-channel sums
__device__ float  g_ps1[32 * 4096];

struct Sel { int s0[64]; int s1[128]; };

__device__ __forceinline__ void warp_red(float& s) {
  for (int o = 16; o; o >>= 1) s += __shfl_down_sync(FULLMASK, s, o);
}

// fence-free: visibility to later kernels via kernel boundary
__device__ __forceinline__ void block_add_double(float val, int slot, double* shd) {
  double d = (double)val;
  for (int o = 16; o; o >>= 1) d += __shfl_down_sync(FULLMASK, d, o);
  int t = threadIdx.x, w = t >> 5;
  if ((t & 31) == 0) shd[w] = d;
  __syncthreads();
  if (t == 0) {
    double s = 0.0;
    for (int i = 0; i < 8; i++) s += shd[i];
    atomicAdd(&g_acc[slot], s);
  }
}

// =========================== K0: f2 norms + l_main ===========================

// f2 norms: block=(b, strip s of 128px). 8 warps x 32 channels.
__device__ void k0_f2norm(const float* __restrict__ f2, int b, int s) {
  int w = threadIdx.x >> 5, lane = threadIdx.x & 31;
  const float* base = f2 + (size_t)b * 256 * 1024 + s * 128;
#pragma unroll
  for (int g = 0; g < 4; g++) {
    float n[8];
#pragma unroll
    for (int r = 0; r < 8; r++) {
      int c = w * 32 + g * 8 + r;
      float4 v = ((const float4*)(base + (size_t)c * 1024))[lane];
      n[r] = v.x * v.x + v.y * v.y + v.z * v.z + v.w * v.w;
    }
#pragma unroll
    for (int r = 0; r < 8; r++) {
      float nn = n[r];
      warp_red(nn);
      if (lane == 0) g_np2[((b * 8 + s) * 256) + w * 32 + g * 8 + r] = nn;
    }
  }
}

// l_main
__device__ void main_body(const float* __restrict__ pred, const int* __restrict__ tgt, int b) {
  __shared__ float sh[8];
  __shared__ float shm;
  int t = threadIdx.x;
  const float* row = pred + b * 1000;
  float m = -1e30f;
  for (int i = t; i < 1000; i += 256) m = fmaxf(m, row[i]);
  for (int o = 16; o; o >>= 1) m = fmaxf(m, __shfl_down_sync(FULLMASK, m, o));
  if ((t & 31) == 0) sh[t >> 5] = m;
  __syncthreads();
  if (t == 0) {
    float mm = sh[0];
    for (int i = 1; i < 8; i++) mm = fmaxf(mm, sh[i]);
    shm = mm;
  }
  __syncthreads();
  m = shm;
  float s = 0.f;
  for (int i = t; i < 1000; i += 256) s += expf(row[i] - m);
  for (int o = 16; o; o >>= 1) s += __shfl_down_sync(FULLMASK, s, o);
  if ((t & 31) == 0) sh[t >> 5] = s;
  __syncthreads();
  if (t == 0) {
    float ss = 0.f;
    for (int i = 0; i < 8; i++) ss += sh[i];
    int tg = tgt[b];
    double lp = (double)(row[tg] - m) - log((double)ss);
    g_main_part[b] = -lp;
  }
}

__global__ void __launch_bounds__(256) k_pass0(
    const float* __restrict__ pred, const float* __restrict__ f2,
    const int* __restrict__ tgt) {
  int bid = blockIdx.x;
  if (bid < 256) { k0_f2norm(f2, bid >> 3, bid & 7); return; }
  main_body(pred, tgt, bid - 256);
}

// =========================== shared ranking helpers ===========================

template <int C>
__device__ __forceinline__ void rank_strong(const float* ns, int* sidx) {
  int t = threadIdx.x;
  if (t < C) {
    float v = ns[t];
    int rank = 0;
#pragma unroll 4
    for (int j = 0; j < C; j++) {
      float nj = ns[j];
      rank += (nj > v) || (nj == v && j < t);   // argsort(-norm), stable
    }
    if (rank < C / 2) sidx[rank] = t;
  }
  __syncthreads();
}

template <int C>
__device__ __forceinline__ void rank_flags(const float* ns, unsigned char* fl) {
  int t = threadIdx.x;
  if (t < C) {
    float v = ns[t];
    int rank = 0;
#pragma unroll 4
    for (int j = 0; j < C; j++) {
      float nj = ns[j];
      rank += (nj > v) || (nj == v && j < t);
    }
    fl[t] = (rank < C / 2) ? (unsigned char)0 : (unsigned char)1;
  }
  __syncthreads();
}

__device__ __forceinline__ float sigmoidf_(float x) { return 1.f / (1.f + expf(-x)); }

// =========================== PASS A (R15 bodies) ===========================

// f0: block=(b, strip s of 512px). 8 warps x 8 channels.
__device__ void passa_f0(float* buf, double* shd, const float* __restrict__ f0,
                         const float* __restrict__ f2, const Sel& sel, int b, int s) {
  int t = threadIdx.x, w = t >> 5, lane = t & 31;
  const float* base = f0 + (size_t)b * 64 * 16384 + s * 512;
  const float* tb = f2 + (size_t)b * 256 * 1024 + s * 32;  // texel row == s
  float4 ps[4];
#pragma unroll
  for (int q = 0; q < 4; q++) ps[q] = make_float4(0.f, 0.f, 0.f, 0.f);
  float n[8];
  float scr = 0.f;
#pragma unroll
  for (int r = 0; r < 8; r++) {
    int c = w * 8 + r;
    const float4* pc = (const float4*)(base + (size_t)c * 16384);
    float tv = tb[(size_t)sel.s0[c] * 1024 + lane];
    float nn = 0.f;
#pragma unroll
    for (int q = 0; q < 4; q++) {
      float4 v = __ldcs(pc + lane + 32 * q);    // evict-first: protect f2 in L2
      ps[q].x += v.x; ps[q].y += v.y; ps[q].z += v.z; ps[q].w += v.w;
      nn += v.x * v.x + v.y * v.y + v.z * v.z + v.w * v.w;
      float d0 = v.x - tv, d1 = v.y - tv, d2 = v.z - tv, d3 = v.w - tv;
      scr += d0 * d0 + d1 * d1 + d2 * d2 + d3 * d3;
    }
    n[r] = nn;
  }
#pragma unroll
  for (int r = 0; r < 8; r++) {
    float nn = n[r];
    warp_red(nn);
    if (lane == 0) g_np0[((b * 32 + s) * 64) + w * 8 + r] = nn;
  }
  float4* b4 = (float4*)(buf + w * 512);
#pragma unroll
  for (int q = 0; q < 4; q++) b4[lane + 32 * q] = ps[q];
  __syncthreads();
  float* gp = g_ps0 + (size_t)b * 16384 + s * 512;
  for (int p = t; p < 512; p += 256) {
    float ss = 0.f;
#pragma unroll
    for (int w2 = 0; w2 < 8; w2++) ss += buf[w2 * 512 + p];
    gp[p] = ss;
  }
  block_add_double(scr, 3, shd);
}

// f1: block=(b, strip s of 256px). 8 warps x 16 channels.
__device__ void passa_f1(float* buf, double* shd, const float* __restrict__ f1,
                         const float* __restrict__ f2, const Sel& sel, int b, int s) {
  int t = threadIdx.x, w = t >> 5, lane = t & 31;
  const float* base = f1 + (size_t)b * 128 * 4096 + s * 256;
  const float* tb = f2 + (size_t)b * 256 * 1024;
  int tcol = (2 * lane) & 31;
  float4 ps0 = make_float4(0.f, 0.f, 0.f, 0.f), ps1 = ps0;
  float n[16];
  float scr = 0.f;
#pragma unroll
  for (int r = 0; r < 16; r++) {
    int c = w * 16 + r;
    const float4* pc = (const float4*)(base + (size_t)c * 4096);
    const float* tc = tb + (size_t)sel.s1[c] * 1024;
    float2 t0 = *(const float2*)(tc + (2 * s) * 32 + tcol);
    float2 t1 = *(const float2*)(tc + (2 * s + 1) * 32 + tcol);
    float4 v0 = __ldcs(pc + lane);
    float4 v1 = __ldcs(pc + lane + 32);
    ps0.x += v0.x; ps0.y += v0.y; ps0.z += v0.z; ps0.w += v0.w;
    ps1.x += v1.x; ps1.y += v1.y; ps1.z += v1.z; ps1.w += v1.w;
    n[r] = v0.x * v0.x + v0.y * v0.y + v0.z * v0.z + v0.w * v0.w
         + v1.x * v1.x + v1.y * v1.y + v1.z * v1.z + v1.w * v1.w;
    float a0 = v0.x - t0.x, a1 = v0.y - t0.x, a2 = v0.z - t0.y, a3 = v0.w - t0.y;
    float b0 = v1.x - t1.x, b1 = v1.y - t1.x, b2 = v1.z - t1.y, b3 = v1.w - t1.y;
    scr += a0 * a0 + a1 * a1 + a2 * a2 + a3 * a3
         + b0 * b0 + b1 * b1 + b2 * b2 + b3 * b3;
  }
#pragma unroll
  for (int r = 0; r < 16; r++) {
    float nn = n[r];
    warp_red(nn);
    if (lane == 0) g_np1[((b * 16 + s) * 128) + w * 16 + r] = nn;
  }
  float4* b4 = (float4*)(buf + w * 256);
  b4[lane] = ps0;
  b4[lane + 32] = ps1;
  __syncthreads();
  float* gp = g_ps1 + (size_t)b * 4096 + s * 256;
  if (t < 256) {
    float ss = 0.f;
#pragma unroll
    for (int w2 = 0; w2 < 8; w2++) ss += buf[w2 * 256 + t];
    gp[t] = ss;
  }
  block_add_double(scr, 4, shd);
}

// f2 IFD inline: block=(b, strip s of 128px). 8 warps x 32 channels.
__device__ void passa_f2ifd(float* buf, double* shd, const float* __restrict__ f2,
                            float* ns, unsigned char* fl, int b, int s) {
  int t = threadIdx.x, w = t >> 5, lane = t & 31;
  {
    float acc = 0.f;
    const float* pp = g_np2 + b * 8 * 256 + t;
#pragma unroll 8
    for (int k = 0; k < 8; k++) acc += pp[k * 256];
    ns[t] = acc;
  }
  __syncthreads();
  rank_flags<256>(ns, fl);

  const float* base = f2 + (size_t)b * 256 * 1024 + s * 128;
  float4 st = make_float4(0.f, 0.f, 0.f, 0.f);
  float4 tt = st;
#pragma unroll 8
  for (int g = 0; g < 32; g++) {
    int c = w * 32 + g;
    float4 v = ((const float4*)(base + (size_t)c * 1024))[lane];
    tt.x += v.x; tt.y += v.y; tt.z += v.z; tt.w += v.w;
    if (!fl[c]) { st.x += v.x; st.y += v.y; st.z += v.z; st.w += v.w; }
  }
  float* bufS = buf;
  float* bufT = buf + 1024;
  *(float4*)(bufS + w * 128 + lane * 4) = st;
  *(float4*)(bufT + w * 128 + lane * 4) = tt;
  __syncthreads();
  float ifd = 0.f;
  if (t < 128) {
    float sS = 0.f, sT = 0.f;
#pragma unroll
    for (int w2 = 0; w2 < 8; w2++) {
      sS += bufS[w2 * 128 + t];
      sT += bufT[w2 * 128 + t];
    }
    const float inv = 1.f / 128.f;
    float d = sigmoidf_((sT - sS) * inv) - sigmoidf_(sS * inv);
    ifd = d * d;
  }
  block_add_double(ifd, 2, shd);
}

__global__ void __launch_bounds__(256) k_passA(
    const float* __restrict__ f0, const float* __restrict__ f1,
    const float* __restrict__ f2, Sel sel) {
  __shared__ __align__(16) float buf[8 * 512];
  __shared__ double shd[8];
  __shared__ float ns[256];
  __shared__ unsigned char fl[256];
  int bid = blockIdx.x;
  // f2 IFD first: f2 is L2-warm from K0
  if (bid < 256)  { passa_f2ifd(buf, shd, f2, ns, fl, bid >> 3, bid & 7); return; }
  bid -= 256;
  if (bid < 1024) { passa_f0(buf, shd, f0, f2, sel, bid >> 5, bid & 31); return; }
  bid -= 1024;
  passa_f1(buf, shd, f1, f2, sel, bid >> 4, bid & 15);
}

// =========================== PASS B (f0/f1 only) ===========================

// f0: 16 blocks/batch, vec4 (1024 px/block), 32 strong planes
__device__ void passb_f0(const float* __restrict__ f0, int b, int pb,
                         float* ns, int* sidx, double* shd) {
  int t = threadIdx.x;
  if (t < 64) {
    float s = 0.f;
    const float* pp = g_np0 + b * 32 * 64 + t;
#pragma unroll 8
    for (int k = 0; k < 32; k++) s += pp[k * 64];
    ns[t] = s;
  }
  __syncthreads();
  rank_strong<64>(ns, sidx);
  int p0 = pb * 1024 + t * 4;
  const float* xb = f0 + (size_t)b * 64 * 16384 + p0;
  float s0 = 0.f, s1 = 0.f, s2 = 0.f, s3 = 0.f;
#pragma unroll 8
  for (int k = 0; k < 32; k++) {
    float4 v = *(const float4*)(xb + (size_t)sidx[k] * 16384);
    s0 += v.x; s1 += v.y; s2 += v.z; s3 += v.w;
  }
  float4 pa = *(const float4*)(g_ps0 + (size_t)b * 16384 + p0);
  const float inv = 1.f / 32.f;
  float d0 = sigmoidf_((pa.x - s0) * inv) - sigmoidf_(s0 * inv);
  float d1 = sigmoidf_((pa.y - s1) * inv) - sigmoidf_(s1 * inv);
  float d2 = sigmoidf_((pa.z - s2) * inv) - sigmoidf_(s2 * inv);
  float d3 = sigmoidf_((pa.w - s3) * inv) - sigmoidf_(s3 * inv);
  block_add_double(d0 * d0 + d1 * d1 + d2 * d2 + d3 * d3, 0, shd);
}

// f1: 8 blocks/batch, vec2 (512 px/block), 64 strong planes
__device__ void passb_f1(const float* __restrict__ f1, int b, int pb,
                         float* ns, int* sidx, double* shd) {
  int t = threadIdx.x;
  if (t < 128) {
    float s = 0.f;
    const float* pp = g_np1 + b * 16 * 128 + t;
#pragma unroll 8
    for (int k = 0; k < 16; k++) s += pp[k * 128];
    ns[t] = s;
  }
  __syncthreads();
  rank_strong<128>(ns, sidx);
  int p0 = pb * 512 + t * 2;
  const float* xb = f1 + (size_t)b * 128 * 4096 + p0;
  float s0 = 0.f, s1 = 0.f;
#pragma unroll 8
  for (int k = 0; k < 64; k++) {
    float2 v = *(const float2*)(xb + (size_t)sidx[k] * 4096);
    s0 += v.x; s1 += v.y;
  }
  float2 pa = *(const float2*)(g_ps1 + (size_t)b * 4096 + p0);
  const float inv = 1.f / 64.f;
  float d0 = sigmoidf_((pa.x - s0) * inv) - sigmoidf_(s0 * inv);
  float d1 = sigmoidf_((pa.y - s1) * inv) - sigmoidf_(s1 * inv);
  block_add_double(d0 * d0 + d1 * d1, 1, shd);
}

__global__ void __launch_bounds__(256) k_passB(
    const float* __restrict__ f0, const float* __restrict__ f1) {
  __shared__ float ns[256];
  __shared__ int sidx[128];
  __shared__ double shd[8];
  int bid = blockIdx.x;
  if (bid < 256) { passb_f1(f1, bid >> 3, bid & 7, ns, sidx, shd); return; }
  bid -= 256;
  passb_f0(f0, bid >> 4, bid & 15, ns, sidx, shd);
}

// =========================== FINAL (parallel loads) ===========================
__global__ void k_final(float* __restrict__ out) {
  __shared__ double sacc[8];
  int t = threadIdx.x;
  // parallel: 32 main-part loads in flight at once + 8 acc loads
  double lm = g_main_part[t];
  if (t < 8) sacc[t] = g_acc[t];
  for (int o = 16; o; o >>= 1) lm += __shfl_down_sync(FULLMASK, lm, o);
  __syncwarp();
  if (t == 0) {
    double l_main = lm / 32.0;
    double ifd0 = sacc[0] / (32.0 * 128.0 * 128.0);
    double ifd1 = sacc[1] / (32.0 * 64.0 * 64.0);
    double ifd2 = sacc[2] / (32.0 * 32.0 * 32.0);
    double l_ifd = (ifd0 + ifd1 + ifd2) / 3.0;
    double scr0 = sacc[3] / (32.0 * 64.0 * 128.0 * 128.0);
    double scr1 = sacc[4] / (32.0 * 128.0 * 64.0 * 64.0);
    double l_scr = (scr0 + scr1) / 2.0;
    double total = l_main + 0.015 * l_scr + 0.015 * l_ifd;
    out[0] = (float)total;
    out[1] = (float)l_main;
    out[2] = (float)l_scr;
    out[3] = (float)l_ifd;
  }
  if (t < 8) g_acc[t] = 0.0;   // reset for next replay
}

// =========================== HOST: constant channel permutations ===========================
static void tf_h(unsigned k0, unsigned k1, unsigned x0, unsigned x1,
                 unsigned* o0, unsigned* o1) {
  unsigned ks2 = 0x1BD11BDAu ^ k0 ^ k1;
#define TFRH(r) { x0 += x1; x1 = (x1 << (r)) | (x1 >> (32 - (r))); x1 ^= x0; }
  x0 += k0; x1 += k1;
  TFRH(13) TFRH(15) TFRH(26) TFRH(6)   x0 += k1;  x1 += ks2 + 1u;
  TFRH(17) TFRH(29) TFRH(16) TFRH(24)  x0 += ks2; x1 += k0 + 2u;
  TFRH(13) TFRH(15) TFRH(26) TFRH(6)   x0 += k0;  x1 += k1 + 3u;
  TFRH(17) TFRH(29) TFRH(16) TFRH(24)  x0 += k1;  x1 += ks2 + 4u;
  TFRH(13) TFRH(15) TFRH(26) TFRH(6)   x0 += ks2; x1 += k0 + 5u;
#undef TFRH
  *o0 = x0; *o1 = x1;
}

static void compute_sel(Sel* S) {
  for (int i = 0; i < 2; i++) {
    unsigned kf0, kf1, a0, a1, b0, b1, c0, c1, d0, d1;
    tf_h(0u, 42u, 0u, (unsigned)i, &kf0, &kf1);
    tf_h(kf0, kf1, 0u, 2u, &a0, &a1);
    tf_h(kf0, kf1, 1u, 3u, &b0, &b1);
    unsigned kt0 = a1, kt1 = b1;
    tf_h(kt0, kt1, 0u, 2u, &c0, &c1);
    tf_h(kt0, kt1, 1u, 3u, &d0, &d1);
    unsigned sk0 = c1, sk1 = d1;
    (void)a0; (void)b0; (void)c0; (void)d0;
    unsigned keys[256];
    for (int j = 0; j < 128; j++) {
      unsigned y0, y1;
      tf_h(sk0, sk1, (unsigned)j, (unsigned)(j + 128), &y0, &y1);
      keys[j] = y0; keys[j + 128] = y1;
    }
    int perm[256];
    for (int t = 0; t < 256; t++) {
      unsigned my = keys[t];
      int rank = 0;
      for (int j = 0; j < 256; j++) {
        unsigned kj = keys[j];
        rank += (kj < my) || (kj == my && j < t);
      }
      perm[rank] = t;
    }
    if (i == 0) { for (int t = 0; t < 64;  t++) S->s0[t] = perm[t]; }
    else        { for (int t = 0; t < 128; t++) S->s1[t] = perm[t]; }
  }
}

extern "C" void kernel_launch(void* const* d_in, const int* in_sizes, int n_in,
                              void* d_out, int out_size) {
  const float* pred = (const float*)d_in[0];
  const float* f0   = (const float*)d_in[1];   // (32, 64, 128, 128)
  const float* f1   = (const float*)d_in[2];   // (32, 128, 64, 64)
  const float* f2   = (const float*)d_in[3];   // (32, 256, 32, 32)
  const int*   tgt  = (const int*)d_in[4];     // int32 (JAX x64 disabled)
  float* out = (float*)d_out;

  Sel sel;
  compute_sel(&sel);                            // deterministic constants

  k_pass0<<<288, 256>>>(pred, f2, tgt);         // 256 f2norm + 32 main; warms L2 with f2
  k_passA<<<1792, 256>>>(f0, f1, f2, sel);      // 256 f2ifd + 1024 f0 + 512 f1
  k_passB<<<768, 256>>>(f0, f1);                // 256 f1 + 512 f0
  k_final<<<1, 32>>>(out);
}